// round 1
// baseline (speedup 1.0000x reference)
#include <cuda_runtime.h>
#include <cuda_bf16.h>

#define HH 128
#define WW 128
#define BB 16
#define HW (HH * WW)

// -------- scratch (static __device__ globals; no runtime allocation) --------
__device__ float g_c1[(size_t)BB * 256 * HW];    // 256 MB  conv1 output
__device__ float g_c2[(size_t)BB * 128 * HW];    // 128 MB  conv2 output
__device__ float g_edge[(size_t)BB * 128 * HW];  // 128 MB  sobel output
__device__ float g_w1f[256 * 64];
__device__ float g_w2f[128 * 256 * 9];
__device__ float g_w3f[64 * 128 * 9];
__device__ float g_b1f[256];
__device__ float g_b2f[128];
__device__ float g_b3f[64];

// -------- fold BN into conv weights/bias --------
// scale = g * rsqrt(v + eps); wf = w * scale[co]; bf = (b - m)*scale + beta
__global__ void fuse_bn_kernel(const float* __restrict__ w, const float* __restrict__ b,
                               const float* __restrict__ g, const float* __restrict__ be,
                               const float* __restrict__ m, const float* __restrict__ v,
                               float* __restrict__ wf, float* __restrict__ bf,
                               int Co, int K) {
    int idx = blockIdx.x * blockDim.x + threadIdx.x;
    int total = Co * K;
    if (idx < total) {
        int co = idx / K;
        float s = g[co] * rsqrtf(v[co] + 1e-5f);
        wf[idx] = w[idx] * s;
    }
    if (idx < Co) {
        float s = g[idx] * rsqrtf(v[idx] + 1e-5f);
        bf[idx] = (b[idx] - m[idx]) * s + be[idx];
    }
}

// -------- implicit-GEMM conv + bias + ReLU --------
// out[b, co, h, w] = relu( sum_{ci,kh,kw} x[b,ci,h+kh-P,w+kw-P] * wf[co, ci*KSZ*KSZ + kh*KSZ + kw] + bf[co] )
// GEMM view: M = Co (tiled 64), N = B*H*W (tiled 64, within one row since W%64==0), K = Ci*KSZ*KSZ.
// 256 threads, BM=BN=64, BK=16, 4x4 register microtile per thread.
template <int KSZ, int PAD>
__global__ __launch_bounds__(256) void conv_kernel(
    const float* __restrict__ x, const float* __restrict__ wf,
    const float* __restrict__ bf, float* __restrict__ out,
    int Ci, long ostrideB) {
    const int K = Ci * KSZ * KSZ;

    __shared__ float As[16][64];  // [k][co]  (transposed weights)
    __shared__ float Bs[16][64];  // [k][pixel]

    const int tid = threadIdx.x;
    const int tx = tid & 15;        // pixel group 0..15
    const int ty = tid >> 4;        // co group    0..15
    const int n0 = blockIdx.x * 64; // first pixel of tile
    const int b = n0 / HW;
    const int rem = n0 - b * HW;
    const int h = rem / WW;
    const int w0 = rem - h * WW;    // tile lies within one row (W % 64 == 0)
    const int co0 = blockIdx.y * 64;

    // B-tile load mapping: 16 k-rows x 64 pixels, 4 pixels/thread
    const int krow = tid >> 4;          // 0..15
    const int wseg = (tid & 15) * 4;    // 0..60
    // A-tile load mapping: 64 co x 16 k, float4 along k per thread
    const int co_a = tid >> 2;          // 0..63
    const int j0 = (tid & 3) * 4;       // 0,4,8,12

    float acc[4][4];
#pragma unroll
    for (int i = 0; i < 4; i++)
#pragma unroll
        for (int j = 0; j < 4; j++) acc[i][j] = 0.f;

    for (int k0 = 0; k0 < K; k0 += 16) {
        // ---- load A tile (weights), store transposed ----
        float4 av = *reinterpret_cast<const float4*>(&wf[(size_t)(co0 + co_a) * K + k0 + j0]);
        As[j0 + 0][co_a] = av.x;
        As[j0 + 1][co_a] = av.y;
        As[j0 + 2][co_a] = av.z;
        As[j0 + 3][co_a] = av.w;

        // ---- load B tile (im2col gather) ----
        int kk = k0 + krow;
        int ci, kh, kw;
        if (KSZ == 1) {
            ci = kk; kh = 0; kw = 0;
        } else {
            ci = kk / 9;
            int r = kk - ci * 9;
            kh = r / 3;
            kw = r - kh * 3;
        }
        int ih = h + kh - PAD;
        const float* xp = x + ((long)(b * Ci + ci) * HH + ih) * WW;
#pragma unroll
        for (int l = 0; l < 4; l++) {
            int iw = w0 + wseg + l + kw - PAD;
            float val = 0.f;
            if (PAD == 0 || ((unsigned)ih < (unsigned)HH && (unsigned)iw < (unsigned)WW))
                val = xp[iw];
            Bs[krow][wseg + l] = val;
        }
        __syncthreads();

        // ---- 16x (lds128 a, lds128 b, 16 FMA) ----
#pragma unroll
        for (int k = 0; k < 16; k++) {
            float4 a = *reinterpret_cast<const float4*>(&As[k][ty * 4]);
            float4 bv = *reinterpret_cast<const float4*>(&Bs[k][tx * 4]);
            float ar[4] = {a.x, a.y, a.z, a.w};
            float br[4] = {bv.x, bv.y, bv.z, bv.w};
#pragma unroll
            for (int i = 0; i < 4; i++)
#pragma unroll
                for (int j = 0; j < 4; j++) acc[i][j] += ar[i] * br[j];
        }
        __syncthreads();
    }

    // ---- epilogue: bias + ReLU, float4 stores ----
#pragma unroll
    for (int i = 0; i < 4; i++) {
        int co = co0 + ty * 4 + i;
        float bias = bf[co];
        float4 o;
        o.x = fmaxf(acc[i][0] + bias, 0.f);
        o.y = fmaxf(acc[i][1] + bias, 0.f);
        o.z = fmaxf(acc[i][2] + bias, 0.f);
        o.w = fmaxf(acc[i][3] + bias, 0.f);
        float* op = out + (size_t)b * ostrideB + (size_t)co * HW + (size_t)h * WW + w0 + tx * 4;
        *reinterpret_cast<float4*>(op) = o;
    }
}

// -------- fixed-kernel depthwise sobel (sum of the 4 sobel variants) --------
__global__ void sobel_kernel(const float* __restrict__ in, float* __restrict__ out, int total) {
    int idx = blockIdx.x * blockDim.x + threadIdx.x;
    if (idx >= total) return;
    int p = idx & (HW - 1);
    int bc = idx >> 14;  // HW = 16384 = 2^14
    int h = p >> 7;      // WW = 128
    int w = p & 127;
    const float* base = in + (size_t)bc * HW;

    const float kern[3][3] = {{2.f, 4.f, 4.f}, {-2.f, 0.f, 2.f}, {-4.f, -4.f, -2.f}};
    float s = 0.f;
#pragma unroll
    for (int kh = 0; kh < 3; kh++) {
        int ih = h + kh - 1;
        if ((unsigned)ih >= (unsigned)HH) continue;
#pragma unroll
        for (int kw = 0; kw < 3; kw++) {
            if (kh == 1 && kw == 1) continue;  // coefficient 0
            int iw = w + kw - 1;
            if ((unsigned)iw >= (unsigned)WW) continue;
            s += kern[kh][kw] * base[ih * WW + iw];
        }
    }
    out[idx] = s;
}

// -------- copy input into output channels [0,64) --------
__global__ void copy_in_kernel(const float* __restrict__ in, float* __restrict__ out) {
    int idx = blockIdx.x * blockDim.x + threadIdx.x;  // float4 index
    const int total = BB * 64 * HW / 4;
    if (idx >= total) return;
    float4 v = reinterpret_cast<const float4*>(in)[idx];
    int fidx = idx * 4;
    int b = fidx / (64 * HW);
    int r = fidx - b * (64 * HW);
    *reinterpret_cast<float4*>(out + (size_t)b * (128 * HW) + r) = v;
}

extern "C" void kernel_launch(void* const* d_in, const int* in_sizes, int n_in,
                              void* d_out, int out_size) {
    const float* input = (const float*)d_in[0];
    const float* w1 = (const float*)d_in[1];
    const float* b1 = (const float*)d_in[2];
    const float* g1 = (const float*)d_in[3];
    const float* be1 = (const float*)d_in[4];
    const float* m1 = (const float*)d_in[5];
    const float* v1 = (const float*)d_in[6];
    const float* w2 = (const float*)d_in[7];
    const float* b2 = (const float*)d_in[8];
    const float* g2 = (const float*)d_in[9];
    const float* be2 = (const float*)d_in[10];
    const float* m2 = (const float*)d_in[11];
    const float* v2 = (const float*)d_in[12];
    const float* w3 = (const float*)d_in[13];
    const float* b3 = (const float*)d_in[14];
    const float* g3 = (const float*)d_in[15];
    const float* be3 = (const float*)d_in[16];
    const float* m3 = (const float*)d_in[17];
    const float* v3 = (const float*)d_in[18];
    float* out = (float*)d_out;

    float *c1, *c2, *edge, *w1f, *w2f, *w3f, *b1f, *b2f, *b3f;
    cudaGetSymbolAddress((void**)&c1, g_c1);
    cudaGetSymbolAddress((void**)&c2, g_c2);
    cudaGetSymbolAddress((void**)&edge, g_edge);
    cudaGetSymbolAddress((void**)&w1f, g_w1f);
    cudaGetSymbolAddress((void**)&w2f, g_w2f);
    cudaGetSymbolAddress((void**)&w3f, g_w3f);
    cudaGetSymbolAddress((void**)&b1f, g_b1f);
    cudaGetSymbolAddress((void**)&b2f, g_b2f);
    cudaGetSymbolAddress((void**)&b3f, g_b3f);

    // ---- fold BN into weights ----
    fuse_bn_kernel<<<(256 * 64 + 255) / 256, 256>>>(w1, b1, g1, be1, m1, v1, w1f, b1f, 256, 64);
    fuse_bn_kernel<<<(128 * 2304 + 255) / 256, 256>>>(w2, b2, g2, be2, m2, v2, w2f, b2f, 128, 2304);
    fuse_bn_kernel<<<(64 * 1152 + 255) / 256, 256>>>(w3, b3, g3, be3, m3, v3, w3f, b3f, 64, 1152);

    // ---- passthrough channels 0..63 ----
    copy_in_kernel<<<(BB * 64 * HW / 4 + 255) / 256, 256>>>(input, out);

    const int NTILES = BB * HW / 64;  // 4096 pixel tiles

    // conv1: 1x1, 64->256, pad 0
    conv_kernel<1, 0><<<dim3(NTILES, 4), 256>>>(input, w1f, b1f, c1, 64, (long)256 * HW);
    // conv2: 3x3, 256->128, pad 1
    conv_kernel<3, 1><<<dim3(NTILES, 2), 256>>>(c1, w2f, b2f, c2, 256, (long)128 * HW);
    // sobel depthwise
    int total = BB * 128 * HW;
    sobel_kernel<<<(total + 255) / 256, 256>>>(c2, edge, total);
    // conv3: 3x3, 128->64, pad 1, writes channels [64,128) of d_out
    conv_kernel<3, 1><<<dim3(NTILES, 1), 256>>>(edge, w3f, b3f, out + (size_t)64 * HW, 128,
                                                (long)128 * HW);
}

// round 2
// speedup vs baseline: 1.7008x; 1.7008x over previous
#include <cuda_runtime.h>
#include <cuda_bf16.h>
#include <cstdint>

#define HH 128
#define WW 128
#define BB 16
#define HW (HH * WW)

// -------- scratch (static __device__ globals; no runtime allocation) --------
__device__ float g_c1[(size_t)BB * 256 * HW];    // 256 MB  conv1 output
__device__ float g_c2[(size_t)BB * 128 * HW];    // 128 MB  conv2 output
__device__ float g_edge[(size_t)BB * 128 * HW];  // 128 MB  sobel output
__device__ float g_w1f[256 * 64];
__device__ float g_w2f[128 * 256 * 9];
__device__ float g_w3f[64 * 128 * 9];
__device__ float g_b1f[256];
__device__ float g_b2f[128];
__device__ float g_b3f[64];

// -------- fold BN into conv weights/bias --------
__global__ void fuse_bn_kernel(const float* __restrict__ w, const float* __restrict__ b,
                               const float* __restrict__ g, const float* __restrict__ be,
                               const float* __restrict__ m, const float* __restrict__ v,
                               float* __restrict__ wf, float* __restrict__ bf,
                               int Co, int K) {
    int idx = blockIdx.x * blockDim.x + threadIdx.x;
    int total = Co * K;
    if (idx < total) {
        int co = idx / K;
        float s = g[co] * rsqrtf(v[co] + 1e-5f);
        wf[idx] = w[idx] * s;
    }
    if (idx < Co) {
        float s = g[idx] * rsqrtf(v[idx] + 1e-5f);
        bf[idx] = (b[idx] - m[idx]) * s + be[idx];
    }
}

// -------- tf32 helpers --------
__device__ __forceinline__ uint32_t f2tf32(float f) {
    uint32_t r;
    asm("cvt.rna.tf32.f32 %0, %1;" : "=r"(r) : "f"(f));
    return r;
}

__device__ __forceinline__ void mma_tf32(float* c, const uint32_t* a, uint32_t b0, uint32_t b1) {
    asm volatile(
        "mma.sync.aligned.m16n8k8.row.col.f32.tf32.tf32.f32 "
        "{%0,%1,%2,%3}, {%4,%5,%6,%7}, {%8,%9}, {%0,%1,%2,%3};\n"
        : "+f"(c[0]), "+f"(c[1]), "+f"(c[2]), "+f"(c[3])
        : "r"(a[0]), "r"(a[1]), "r"(a[2]), "r"(a[3]), "r"(b0), "r"(b1));
}

// -------- TF32 tensor-core implicit-GEMM conv + bias + ReLU --------
// GEMM: M = Co (<=128 per block), N = B*H*W (BN=128 = one image row), K = Ci*KSZ*KSZ.
// BM=128, BN=128, BK=32. 256 threads = 8 warps, warp tile 32x64 (2x8 m16n8k8 tiles).
// As[m][k] pad->36, Bs[k][n] pad->136 : both fragment-load patterns bank-conflict-free.
template <int KSZ, int PAD>
__global__ __launch_bounds__(256) void conv_mma_kernel(
    const float* __restrict__ x, const float* __restrict__ wf,
    const float* __restrict__ bf, float* __restrict__ out,
    int Ci, int Co, long ostrideB) {
    const int K = Ci * KSZ * KSZ;

    __shared__ float As[128][36];   // [m][k]
    __shared__ float Bs[32][136];   // [k][n]

    const int tid = threadIdx.x;
    const int lane = tid & 31;
    const int wid = tid >> 5;
    const int warp_m = wid & 3;   // 0..3  -> 32 rows each
    const int warp_n = wid >> 2;  // 0..1  -> 64 cols each

    const int n0 = blockIdx.x * 128;
    const int b = n0 >> 14;             // / HW
    const int h = (n0 & (HW - 1)) >> 7; // / WW
    const int co0 = blockIdx.y * 128;

    // B-tile load mapping: kr = k-row (0..31), 16 consecutive pixels per thread
    const int kr = tid >> 3;
    const int wbase = (tid & 7) * 16;

    float acc[2][8][4];
#pragma unroll
    for (int i = 0; i < 2; i++)
#pragma unroll
        for (int j = 0; j < 8; j++)
#pragma unroll
            for (int r = 0; r < 4; r++) acc[i][j][r] = 0.f;

    const int gid = lane >> 2;   // groupID
    const int tig = lane & 3;    // thread-in-group

    for (int k0 = 0; k0 < K; k0 += 32) {
        // ---- A tile: 128 rows x 32 k, float4 along k, tf32-converted ----
#pragma unroll
        for (int i = 0; i < 4; i++) {
            int lin = i * 256 + tid;
            int row = lin >> 3;
            int c4 = (lin & 7) * 4;
            float4 v = make_float4(0.f, 0.f, 0.f, 0.f);
            if (co0 + row < Co)
                v = *reinterpret_cast<const float4*>(&wf[(size_t)(co0 + row) * K + k0 + c4]);
            uint4 t;
            t.x = f2tf32(v.x); t.y = f2tf32(v.y); t.z = f2tf32(v.z); t.w = f2tf32(v.w);
            *reinterpret_cast<uint4*>(&As[row][c4]) = t;
        }

        // ---- B tile: im2col gather, tf32-converted ----
        {
            int kk = k0 + kr;
            int ci, kh, kw;
            if (KSZ == 1) {
                ci = kk; kh = 0; kw = 0;
            } else {
                ci = kk / 9;
                int r = kk - ci * 9;
                kh = r / 3;
                kw = r - kh * 3;
            }
            int ih = h + kh - PAD;
            const float* xp = x + ((size_t)(b * Ci + ci) * HH + ih) * WW;
            bool hok = (PAD == 0) || ((unsigned)ih < (unsigned)HH);
#pragma unroll
            for (int l = 0; l < 16; l++) {
                int iw = wbase + l + kw - PAD;
                float val = 0.f;
                if (hok && (PAD == 0 || (unsigned)iw < (unsigned)WW)) val = xp[iw];
                reinterpret_cast<uint32_t&>(Bs[kr][wbase + l]) = f2tf32(val);
            }
        }
        __syncthreads();

        // ---- 4 k-steps of m16n8k8 ----
#pragma unroll
        for (int ks = 0; ks < 4; ks++) {
            const int kb = ks * 8;
            uint32_t a[2][4];
#pragma unroll
            for (int tm = 0; tm < 2; tm++) {
                int m0 = warp_m * 32 + tm * 16;
                a[tm][0] = reinterpret_cast<uint32_t&>(As[m0 + gid][kb + tig]);
                a[tm][1] = reinterpret_cast<uint32_t&>(As[m0 + 8 + gid][kb + tig]);
                a[tm][2] = reinterpret_cast<uint32_t&>(As[m0 + gid][kb + 4 + tig]);
                a[tm][3] = reinterpret_cast<uint32_t&>(As[m0 + 8 + gid][kb + 4 + tig]);
            }
#pragma unroll
            for (int tn = 0; tn < 8; tn++) {
                int nc = warp_n * 64 + tn * 8 + gid;
                uint32_t b0 = reinterpret_cast<uint32_t&>(Bs[kb + tig][nc]);
                uint32_t b1 = reinterpret_cast<uint32_t&>(Bs[kb + 4 + tig][nc]);
                mma_tf32(acc[0][tn], a[0], b0, b1);
                mma_tf32(acc[1][tn], a[1], b0, b1);
            }
        }
        __syncthreads();
    }

    // ---- epilogue: bias + ReLU, float2 stores ----
#pragma unroll
    for (int tm = 0; tm < 2; tm++) {
#pragma unroll
        for (int half = 0; half < 2; half++) {
            int co = co0 + warp_m * 32 + tm * 16 + half * 8 + gid;
            if (co < Co) {
                float bias = bf[co];
                float* op = out + (size_t)b * ostrideB + (size_t)co * HW + (size_t)h * WW;
#pragma unroll
                for (int tn = 0; tn < 8; tn++) {
                    int w = warp_n * 64 + tn * 8 + tig * 2;
                    float2 o;
                    o.x = fmaxf(acc[tm][tn][half * 2 + 0] + bias, 0.f);
                    o.y = fmaxf(acc[tm][tn][half * 2 + 1] + bias, 0.f);
                    *reinterpret_cast<float2*>(op + w) = o;
                }
            }
        }
    }
}

// -------- fixed-kernel depthwise sobel (exact fp32) --------
__global__ void sobel_kernel(const float* __restrict__ in, float* __restrict__ out, int total) {
    int idx = blockIdx.x * blockDim.x + threadIdx.x;
    if (idx >= total) return;
    int p = idx & (HW - 1);
    int bc = idx >> 14;
    int h = p >> 7;
    int w = p & 127;
    const float* base = in + (size_t)bc * HW;

    const float kern[3][3] = {{2.f, 4.f, 4.f}, {-2.f, 0.f, 2.f}, {-4.f, -4.f, -2.f}};
    float s = 0.f;
#pragma unroll
    for (int kh = 0; kh < 3; kh++) {
        int ih = h + kh - 1;
        if ((unsigned)ih >= (unsigned)HH) continue;
#pragma unroll
        for (int kw = 0; kw < 3; kw++) {
            if (kh == 1 && kw == 1) continue;
            int iw = w + kw - 1;
            if ((unsigned)iw >= (unsigned)WW) continue;
            s += kern[kh][kw] * base[ih * WW + iw];
        }
    }
    out[idx] = s;
}

// -------- copy input into output channels [0,64) --------
__global__ void copy_in_kernel(const float* __restrict__ in, float* __restrict__ out) {
    int idx = blockIdx.x * blockDim.x + threadIdx.x;
    const int total = BB * 64 * HW / 4;
    if (idx >= total) return;
    float4 v = reinterpret_cast<const float4*>(in)[idx];
    int fidx = idx * 4;
    int b = fidx / (64 * HW);
    int r = fidx - b * (64 * HW);
    *reinterpret_cast<float4*>(out + (size_t)b * (128 * HW) + r) = v;
}

extern "C" void kernel_launch(void* const* d_in, const int* in_sizes, int n_in,
                              void* d_out, int out_size) {
    const float* input = (const float*)d_in[0];
    const float* w1 = (const float*)d_in[1];
    const float* b1 = (const float*)d_in[2];
    const float* g1 = (const float*)d_in[3];
    const float* be1 = (const float*)d_in[4];
    const float* m1 = (const float*)d_in[5];
    const float* v1 = (const float*)d_in[6];
    const float* w2 = (const float*)d_in[7];
    const float* b2 = (const float*)d_in[8];
    const float* g2 = (const float*)d_in[9];
    const float* be2 = (const float*)d_in[10];
    const float* m2 = (const float*)d_in[11];
    const float* v2 = (const float*)d_in[12];
    const float* w3 = (const float*)d_in[13];
    const float* b3 = (const float*)d_in[14];
    const float* g3 = (const float*)d_in[15];
    const float* be3 = (const float*)d_in[16];
    const float* m3 = (const float*)d_in[17];
    const float* v3 = (const float*)d_in[18];
    float* out = (float*)d_out;

    float *c1, *c2, *edge, *w1f, *w2f, *w3f, *b1f, *b2f, *b3f;
    cudaGetSymbolAddress((void**)&c1, g_c1);
    cudaGetSymbolAddress((void**)&c2, g_c2);
    cudaGetSymbolAddress((void**)&edge, g_edge);
    cudaGetSymbolAddress((void**)&w1f, g_w1f);
    cudaGetSymbolAddress((void**)&w2f, g_w2f);
    cudaGetSymbolAddress((void**)&w3f, g_w3f);
    cudaGetSymbolAddress((void**)&b1f, g_b1f);
    cudaGetSymbolAddress((void**)&b2f, g_b2f);
    cudaGetSymbolAddress((void**)&b3f, g_b3f);

    // ---- fold BN into weights ----
    fuse_bn_kernel<<<(256 * 64 + 255) / 256, 256>>>(w1, b1, g1, be1, m1, v1, w1f, b1f, 256, 64);
    fuse_bn_kernel<<<(128 * 2304 + 255) / 256, 256>>>(w2, b2, g2, be2, m2, v2, w2f, b2f, 128, 2304);
    fuse_bn_kernel<<<(64 * 1152 + 255) / 256, 256>>>(w3, b3, g3, be3, m3, v3, w3f, b3f, 64, 1152);

    // ---- passthrough channels 0..63 ----
    copy_in_kernel<<<(BB * 64 * HW / 4 + 255) / 256, 256>>>(input, out);

    const int NTILES = BB * HW / 128;  // 2048 row tiles

    // conv1: 1x1, 64->256, pad 0 (2 M-blocks)
    conv_mma_kernel<1, 0><<<dim3(NTILES, 2), 256>>>(input, w1f, b1f, c1, 64, 256, (long)256 * HW);
    // conv2: 3x3, 256->128, pad 1
    conv_mma_kernel<3, 1><<<dim3(NTILES, 1), 256>>>(c1, w2f, b2f, c2, 256, 128, (long)128 * HW);
    // sobel depthwise (exact fp32)
    int total = BB * 128 * HW;
    sobel_kernel<<<(total + 255) / 256, 256>>>(c2, edge, total);
    // conv3: 3x3, 128->64, pad 1, writes channels [64,128) of d_out
    conv_mma_kernel<3, 1><<<dim3(NTILES, 1), 256>>>(edge, w3f, b3f, out + (size_t)64 * HW, 128, 64,
                                                    (long)128 * HW);
}

// round 4
// speedup vs baseline: 1.7066x; 1.0034x over previous
#include <cuda_runtime.h>
#include <cuda_bf16.h>
#include <cstdint>

#define HH 128
#define WW 128
#define BB 16
#define HW (HH * WW)

// -------- scratch (static __device__ globals; no runtime allocation) --------
__device__ float g_c1[(size_t)BB * 256 * HW];    // 256 MB  conv1 output
__device__ float g_c2[(size_t)BB * 128 * HW];    // 128 MB  conv2 output
__device__ float g_edge[(size_t)BB * 128 * HW];  // 128 MB  sobel output
__device__ float g_w1f[256 * 64];
__device__ float g_w2f[128 * 256 * 9];
__device__ float g_w3f[64 * 128 * 9];
__device__ float g_b1f[256];
__device__ float g_b2f[128];
__device__ float g_b3f[64];

// -------- fold BN into conv weights/bias --------
__global__ void fuse_bn_kernel(const float* __restrict__ w, const float* __restrict__ b,
                               const float* __restrict__ g, const float* __restrict__ be,
                               const float* __restrict__ m, const float* __restrict__ v,
                               float* __restrict__ wf, float* __restrict__ bf,
                               int Co, int K) {
    int idx = blockIdx.x * blockDim.x + threadIdx.x;
    int total = Co * K;
    if (idx < total) {
        int co = idx / K;
        float s = g[co] * rsqrtf(v[co] + 1e-5f);
        wf[idx] = w[idx] * s;
    }
    if (idx < Co) {
        float s = g[idx] * rsqrtf(v[idx] + 1e-5f);
        bf[idx] = (b[idx] - m[idx]) * s + be[idx];
    }
}

// -------- tf32 helpers --------
__device__ __forceinline__ uint32_t f2tf32(float f) {
    uint32_t r;
    asm("cvt.rna.tf32.f32 %0, %1;" : "=r"(r) : "f"(f));
    return r;
}

__device__ __forceinline__ void mma_tf32(float* c, const uint32_t* a, uint32_t b0, uint32_t b1) {
    asm volatile(
        "mma.sync.aligned.m16n8k8.row.col.f32.tf32.tf32.f32 "
        "{%0,%1,%2,%3}, {%4,%5,%6,%7}, {%8,%9}, {%0,%1,%2,%3};\n"
        : "+f"(c[0]), "+f"(c[1]), "+f"(c[2]), "+f"(c[3])
        : "r"(a[0]), "r"(a[1]), "r"(a[2]), "r"(a[3]), "r"(b0), "r"(b1));
}

// -------- TF32 tensor-core implicit-GEMM conv + bias + ReLU --------
// GEMM: M = Co (<=128 per block), N = B*H*W (BN=128 = one image row), K = Ci*KSZ*KSZ.
// BM=128, BN=128, BK=32. 256 threads = 8 warps, warp tile 32x64 (2x8 m16n8k8 tiles).
// As[m][k] pad->36, Bs[k][n] pad->136 : both fragment-load patterns bank-conflict-free.
template <int KSZ, int PAD>
__global__ __launch_bounds__(256) void conv_mma_kernel(
    const float* __restrict__ x, const float* __restrict__ wf,
    const float* __restrict__ bf, float* __restrict__ out,
    int Ci, int Co, long ostrideB) {
    const int K = Ci * KSZ * KSZ;

    __shared__ float As[128][36];   // [m][k]
    __shared__ float Bs[32][136];   // [k][n]

    const int tid = threadIdx.x;
    const int lane = tid & 31;
    const int wid = tid >> 5;
    const int warp_m = wid & 3;   // 0..3  -> 32 rows each
    const int warp_n = wid >> 2;  // 0..1  -> 64 cols each

    const int n0 = blockIdx.x * 128;
    const int b = n0 >> 14;             // / HW
    const int h = (n0 & (HW - 1)) >> 7; // / WW
    const int co0 = blockIdx.y * 128;

    // B-tile load mapping: kr = k-row (0..31), 16 consecutive pixels per thread
    const int kr = tid >> 3;
    const int wbase = (tid & 7) * 16;

    float acc[2][8][4];
#pragma unroll
    for (int i = 0; i < 2; i++)
#pragma unroll
        for (int j = 0; j < 8; j++)
#pragma unroll
            for (int r = 0; r < 4; r++) acc[i][j][r] = 0.f;

    const int gid = lane >> 2;   // groupID
    const int tig = lane & 3;    // thread-in-group

    for (int k0 = 0; k0 < K; k0 += 32) {
        // ---- A tile: 128 rows x 32 k, float4 along k, tf32-converted ----
#pragma unroll
        for (int i = 0; i < 4; i++) {
            int lin = i * 256 + tid;
            int row = lin >> 3;
            int c4 = (lin & 7) * 4;
            float4 v = make_float4(0.f, 0.f, 0.f, 0.f);
            if (co0 + row < Co)
                v = *reinterpret_cast<const float4*>(&wf[(size_t)(co0 + row) * K + k0 + c4]);
            uint4 t;
            t.x = f2tf32(v.x); t.y = f2tf32(v.y); t.z = f2tf32(v.z); t.w = f2tf32(v.w);
            *reinterpret_cast<uint4*>(&As[row][c4]) = t;
        }

        // ---- B tile: im2col gather, tf32-converted ----
        {
            int kk = k0 + kr;
            int ci, kh, kw;
            if (KSZ == 1) {
                ci = kk; kh = 0; kw = 0;
            } else {
                ci = kk / 9;
                int r = kk - ci * 9;
                kh = r / 3;
                kw = r - kh * 3;
            }
            int ih = h + kh - PAD;
            const float* xp = x + ((size_t)(b * Ci + ci) * HH + ih) * WW;
            bool hok = (PAD == 0) || ((unsigned)ih < (unsigned)HH);
#pragma unroll
            for (int l = 0; l < 16; l++) {
                int iw = wbase + l + kw - PAD;
                float val = 0.f;
                if (hok && (PAD == 0 || (unsigned)iw < (unsigned)WW)) val = xp[iw];
                reinterpret_cast<uint32_t&>(Bs[kr][wbase + l]) = f2tf32(val);
            }
        }
        __syncthreads();

        // ---- 4 k-steps of m16n8k8 ----
#pragma unroll
        for (int ks = 0; ks < 4; ks++) {
            const int kb = ks * 8;
            uint32_t a[2][4];
#pragma unroll
            for (int tm = 0; tm < 2; tm++) {
                int m0 = warp_m * 32 + tm * 16;
                a[tm][0] = reinterpret_cast<uint32_t&>(As[m0 + gid][kb + tig]);
                a[tm][1] = reinterpret_cast<uint32_t&>(As[m0 + 8 + gid][kb + tig]);
                a[tm][2] = reinterpret_cast<uint32_t&>(As[m0 + gid][kb + 4 + tig]);
                a[tm][3] = reinterpret_cast<uint32_t&>(As[m0 + 8 + gid][kb + 4 + tig]);
            }
#pragma unroll
            for (int tn = 0; tn < 8; tn++) {
                int nc = warp_n * 64 + tn * 8 + gid;
                uint32_t b0 = reinterpret_cast<uint32_t&>(Bs[kb + tig][nc]);
                uint32_t b1 = reinterpret_cast<uint32_t&>(Bs[kb + 4 + tig][nc]);
                mma_tf32(acc[0][tn], a[0], b0, b1);
                mma_tf32(acc[1][tn], a[1], b0, b1);
            }
        }
        __syncthreads();
    }

    // ---- epilogue: bias + ReLU, float2 stores ----
#pragma unroll
    for (int tm = 0; tm < 2; tm++) {
#pragma unroll
        for (int half = 0; half < 2; half++) {
            int co = co0 + warp_m * 32 + tm * 16 + half * 8 + gid;
            if (co < Co) {
                float bias = bf[co];
                float* op = out + (size_t)b * ostrideB + (size_t)co * HW + (size_t)h * WW;
#pragma unroll
                for (int tn = 0; tn < 8; tn++) {
                    int w = warp_n * 64 + tn * 8 + tig * 2;
                    float2 o;
                    o.x = fmaxf(acc[tm][tn][half * 2 + 0] + bias, 0.f);
                    o.y = fmaxf(acc[tm][tn][half * 2 + 1] + bias, 0.f);
                    *reinterpret_cast<float2*>(op + w) = o;
                }
            }
        }
    }
}

// -------- fixed-kernel depthwise sobel (exact fp32) --------
__global__ void sobel_kernel(const float* __restrict__ in, float* __restrict__ out, int total) {
    int idx = blockIdx.x * blockDim.x + threadIdx.x;
    if (idx >= total) return;
    int p = idx & (HW - 1);
    int bc = idx >> 14;
    int h = p >> 7;
    int w = p & 127;
    const float* base = in + (size_t)bc * HW;

    const float kern[3][3] = {{2.f, 4.f, 4.f}, {-2.f, 0.f, 2.f}, {-4.f, -4.f, -2.f}};
    float s = 0.f;
#pragma unroll
    for (int kh = 0; kh < 3; kh++) {
        int ih = h + kh - 1;
        if ((unsigned)ih >= (unsigned)HH) continue;
#pragma unroll
        for (int kw = 0; kw < 3; kw++) {
            if (kh == 1 && kw == 1) continue;
            int iw = w + kw - 1;
            if ((unsigned)iw >= (unsigned)WW) continue;
            s += kern[kh][kw] * base[ih * WW + iw];
        }
    }
    out[idx] = s;
}

// -------- copy input into output channels [0,64) --------
__global__ void copy_in_kernel(const float* __restrict__ in, float* __restrict__ out) {
    int idx = blockIdx.x * blockDim.x + threadIdx.x;
    const int total = BB * 64 * HW / 4;
    if (idx >= total) return;
    float4 v = reinterpret_cast<const float4*>(in)[idx];
    int fidx = idx * 4;
    int b = fidx / (64 * HW);
    int r = fidx - b * (64 * HW);
    *reinterpret_cast<float4*>(out + (size_t)b * (128 * HW) + r) = v;
}

extern "C" void kernel_launch(void* const* d_in, const int* in_sizes, int n_in,
                              void* d_out, int out_size) {
    const float* input = (const float*)d_in[0];
    const float* w1 = (const float*)d_in[1];
    const float* b1 = (const float*)d_in[2];
    const float* g1 = (const float*)d_in[3];
    const float* be1 = (const float*)d_in[4];
    const float* m1 = (const float*)d_in[5];
    const float* v1 = (const float*)d_in[6];
    const float* w2 = (const float*)d_in[7];
    const float* b2 = (const float*)d_in[8];
    const float* g2 = (const float*)d_in[9];
    const float* be2 = (const float*)d_in[10];
    const float* m2 = (const float*)d_in[11];
    const float* v2 = (const float*)d_in[12];
    const float* w3 = (const float*)d_in[13];
    const float* b3 = (const float*)d_in[14];
    const float* g3 = (const float*)d_in[15];
    const float* be3 = (const float*)d_in[16];
    const float* m3 = (const float*)d_in[17];
    const float* v3 = (const float*)d_in[18];
    float* out = (float*)d_out;

    float *c1, *c2, *edge, *w1f, *w2f, *w3f, *b1f, *b2f, *b3f;
    cudaGetSymbolAddress((void**)&c1, g_c1);
    cudaGetSymbolAddress((void**)&c2, g_c2);
    cudaGetSymbolAddress((void**)&edge, g_edge);
    cudaGetSymbolAddress((void**)&w1f, g_w1f);
    cudaGetSymbolAddress((void**)&w2f, g_w2f);
    cudaGetSymbolAddress((void**)&w3f, g_w3f);
    cudaGetSymbolAddress((void**)&b1f, g_b1f);
    cudaGetSymbolAddress((void**)&b2f, g_b2f);
    cudaGetSymbolAddress((void**)&b3f, g_b3f);

    // ---- fold BN into weights ----
    fuse_bn_kernel<<<(256 * 64 + 255) / 256, 256>>>(w1, b1, g1, be1, m1, v1, w1f, b1f, 256, 64);
    fuse_bn_kernel<<<(128 * 2304 + 255) / 256, 256>>>(w2, b2, g2, be2, m2, v2, w2f, b2f, 128, 2304);
    fuse_bn_kernel<<<(64 * 1152 + 255) / 256, 256>>>(w3, b3, g3, be3, m3, v3, w3f, b3f, 64, 1152);

    // ---- passthrough channels 0..63 ----
    copy_in_kernel<<<(BB * 64 * HW / 4 + 255) / 256, 256>>>(input, out);

    const int NTILES = BB * HW / 128;  // 2048 row tiles

    // conv1: 1x1, 64->256, pad 0 (2 M-blocks)
    conv_mma_kernel<1, 0><<<dim3(NTILES, 2), 256>>>(input, w1f, b1f, c1, 64, 256, (long)256 * HW);
    // conv2: 3x3, 256->128, pad 1
    conv_mma_kernel<3, 1><<<dim3(NTILES, 1), 256>>>(c1, w2f, b2f, c2, 256, 128, (long)128 * HW);
    // sobel depthwise (exact fp32)
    int total = BB * 128 * HW;
    sobel_kernel<<<(total + 255) / 256, 256>>>(c2, edge, total);
    // conv3: 3x3, 128->64, pad 1, writes channels [64,128) of d_out
    conv_mma_kernel<3, 1><<<dim3(NTILES, 1), 256>>>(edge, w3f, b3f, out + (size_t)64 * HW, 128, 64,
                                                    (long)128 * HW);
}